// round 3
// baseline (speedup 1.0000x reference)
#include <cuda_runtime.h>
#include <cuda_bf16.h>

#define N_NODES 100000
#define N_EDGES 1600000
#define F_IN 128
#define F_OUT 64
#define BN_EPS 1e-5f

// ---------------- scratch (device globals; re-initialized every launch) ----------------
__device__ __align__(16) float g_h[N_NODES * F_OUT];     // 25.6 MB: x @ W^T
__device__ __align__(16) float g_dinv[N_NODES];
__device__ __align__(16) int   g_deg[N_NODES];           // src-occurrence degree (incl. self loop)
__device__ __align__(16) int   g_cnt[N_NODES];           // in-degree by dst (edges only)
__device__ __align__(16) int   g_rowptr[N_NODES + 1];
__device__ __align__(16) int   g_cursor[N_NODES];
__device__ __align__(16) int   g_srcidx[N_EDGES];
__device__ __align__(16) float g_coef[N_EDGES];
__device__ __align__(16) int   g_bsum[128];
__device__ __align__(16) float g_sum[F_OUT];
__device__ __align__(16) float g_sumsq[F_OUT];
__device__ __align__(16) float g_scale[F_OUT];
__device__ __align__(16) float g_shift[F_OUT];

// ---------------- init ----------------
__global__ void k_init() {
    int i = blockIdx.x * blockDim.x + threadIdx.x;
    if (i < N_NODES) {
        g_deg[i] = 1;   // self loop contributes 1 to src-degree
        g_cnt[i] = 0;
    }
    if (i < F_OUT) {
        g_sum[i] = 0.f;
        g_sumsq[i] = 0.f;
    }
}

// ---------------- degree + dst histogram (edge_index is int32!) ----------------
__global__ void k_degcnt(const int* __restrict__ ei) {
    int e = blockIdx.x * blockDim.x + threadIdx.x;
    if (e >= N_EDGES) return;
    int s = ei[e];
    int d = ei[N_EDGES + e];
    atomicAdd(&g_deg[s], 1);
    atomicAdd(&g_cnt[d], 1);
}

__global__ void k_dinv() {
    int i = blockIdx.x * blockDim.x + threadIdx.x;
    if (i < N_NODES) g_dinv[i] = rsqrtf((float)g_deg[i]);
}

// ---------------- 2-level exclusive scan of g_cnt -> g_rowptr ----------------
__global__ void k_scan1() {   // 98 blocks x 1024: block sums
    __shared__ int s[1024];
    int i = blockIdx.x * 1024 + threadIdx.x;
    int v = (i < N_NODES) ? g_cnt[i] : 0;
    s[threadIdx.x] = v;
    __syncthreads();
    for (int off = 512; off > 0; off >>= 1) {
        if (threadIdx.x < off) s[threadIdx.x] += s[threadIdx.x + off];
        __syncthreads();
    }
    if (threadIdx.x == 0) g_bsum[blockIdx.x] = s[0];
}

__global__ void k_scan2(int nblocks) {  // 1 thread: serial exclusive scan of block sums
    if (threadIdx.x == 0) {
        int acc = 0;
        for (int b = 0; b < nblocks; b++) {
            int v = g_bsum[b];
            g_bsum[b] = acc;
            acc += v;
        }
        g_rowptr[N_NODES] = acc;   // == N_EDGES
    }
}

__global__ void k_scan3() {   // 98 blocks x 1024: in-block exclusive scan + block offset
    __shared__ int s[1024];
    int i = blockIdx.x * 1024 + threadIdx.x;
    int v = (i < N_NODES) ? g_cnt[i] : 0;
    s[threadIdx.x] = v;
    __syncthreads();
    for (int off = 1; off < 1024; off <<= 1) {
        int t = (threadIdx.x >= off) ? s[threadIdx.x - off] : 0;
        __syncthreads();
        s[threadIdx.x] += t;
        __syncthreads();
    }
    if (i < N_NODES) {
        int out = g_bsum[blockIdx.x] + s[threadIdx.x] - v;  // exclusive
        g_rowptr[i] = out;
        g_cursor[i] = out;
    }
}

// ---------------- scatter edges into CSR slots ----------------
__global__ void k_scatter(const int* __restrict__ ei,
                          const float* __restrict__ ew) {
    int e = blockIdx.x * blockDim.x + threadIdx.x;
    if (e >= N_EDGES) return;
    int s = ei[e];
    int d = ei[N_EDGES + e];
    float c = g_dinv[s] * ew[e] * g_dinv[d];
    int p = atomicAdd(&g_cursor[d], 1);
    g_srcidx[p] = s;
    g_coef[p] = c;
}

// ---------------- GEMM: h = x @ W^T  (fp32, smem-tiled, 40KB smem) ----------------
// block = 128 threads handles 16 nodes; each thread: 2 nodes x 4 outs.
__global__ __launch_bounds__(128) void k_gemm(const float* __restrict__ x,
                                              const float* __restrict__ W) {
    __shared__ float sW[F_IN * F_OUT];   // transposed: sW[k*64+o], 32 KB
    __shared__ float sX[16 * F_IN];      // 8 KB
    int tid = threadIdx.x;

    for (int i = tid; i < F_OUT * F_IN; i += 128) {
        int o = i / F_IN, k = i % F_IN;
        sW[k * F_OUT + o] = W[i];
    }
    int nodeBase = blockIdx.x * 16;
    const float4* x4 = (const float4*)(x + (size_t)nodeBase * F_IN);
    float4* sX4 = (float4*)sX;
    for (int i = tid; i < 16 * F_IN / 4; i += 128) sX4[i] = x4[i];
    __syncthreads();

    int og = tid & 15;        // out group: outs og*4..og*4+3
    int ng = tid >> 4;        // node group: nodes ng*2..ng*2+1
    float acc[2][4];
    #pragma unroll
    for (int a = 0; a < 2; a++)
        #pragma unroll
        for (int b = 0; b < 4; b++) acc[a][b] = 0.f;

    #pragma unroll 4
    for (int k = 0; k < F_IN; k++) {
        float4 w4 = *(const float4*)&sW[k * F_OUT + og * 4];
        #pragma unroll
        for (int ni = 0; ni < 2; ni++) {
            float xv = sX[(ng * 2 + ni) * F_IN + k];
            acc[ni][0] += xv * w4.x;
            acc[ni][1] += xv * w4.y;
            acc[ni][2] += xv * w4.z;
            acc[ni][3] += xv * w4.w;
        }
    }
    #pragma unroll
    for (int ni = 0; ni < 2; ni++) {
        int node = nodeBase + ng * 2 + ni;
        *(float4*)&g_h[(size_t)node * F_OUT + og * 4] =
            make_float4(acc[ni][0], acc[ni][1], acc[ni][2], acc[ni][3]);
    }
}

// ---------------- aggregation: one warp per node, float2 per lane ----------------
// out[d] = relu( sum_{e: dst=d} coef*h[src] + dinv[d]^2 * h[d] ), plus BN partial sums.
// No shared atomics: per-warp staging rows, tree-summed by first 64 threads.
__global__ __launch_bounds__(256) void k_agg(float* __restrict__ out) {
    __shared__ float s_psum[8][F_OUT];
    __shared__ float s_psq[8][F_OUT];
    int tid = threadIdx.x;
    int warp = tid >> 5;
    int lane = tid & 31;
    int node = blockIdx.x * 8 + warp;   // 12500 blocks * 8 = 100000 exactly

    const float2* h2 = (const float2*)g_h;
    float ax, ay;

    // self loop: norm = dinv[n] * 1 * dinv[n]
    {
        float di = g_dinv[node];
        float c = di * di;
        float2 hv = h2[(size_t)node * 32 + lane];
        ax = hv.x * c;
        ay = hv.y * c;
    }
    int beg = g_rowptr[node];
    int end = g_rowptr[node + 1];
    for (int e = beg; e < end; e++) {
        int s = g_srcidx[e];        // uniform across warp -> broadcast
        float c = g_coef[e];
        float2 hv = h2[(size_t)s * 32 + lane];
        ax += hv.x * c;
        ay += hv.y * c;
    }
    ax = fmaxf(ax, 0.f);
    ay = fmaxf(ay, 0.f);

    ((float2*)out)[(size_t)node * 32 + lane] = make_float2(ax, ay);

    s_psum[warp][2 * lane]     = ax;
    s_psum[warp][2 * lane + 1] = ay;
    s_psq[warp][2 * lane]      = ax * ax;
    s_psq[warp][2 * lane + 1]  = ay * ay;
    __syncthreads();
    if (tid < F_OUT) {
        float a = 0.f, b = 0.f;
        #pragma unroll
        for (int w = 0; w < 8; w++) {
            a += s_psum[w][tid];
            b += s_psq[w][tid];
        }
        atomicAdd(&g_sum[tid], a);
        atomicAdd(&g_sumsq[tid], b);
    }
}

// ---------------- BN params + apply ----------------
__global__ void k_bnparam(const float* __restrict__ gamma,
                          const float* __restrict__ beta) {
    int f = threadIdx.x;
    if (f >= F_OUT) return;
    float invN = 1.0f / (float)N_NODES;
    float mean = g_sum[f] * invN;
    float var = g_sumsq[f] * invN - mean * mean;
    float sc = gamma[f] * rsqrtf(var + BN_EPS);
    g_scale[f] = sc;
    g_shift[f] = beta[f] - mean * sc;
}

__global__ void k_bnapply(float* __restrict__ out) {
    int i = blockIdx.x * blockDim.x + threadIdx.x;   // float4 index
    if (i >= N_NODES * F_OUT / 4) return;
    int f4 = i & 15;  // 16 float4 per row of 64
    float4 v = ((float4*)out)[i];
    float4 sc = ((const float4*)g_scale)[f4];
    float4 sh = ((const float4*)g_shift)[f4];
    v.x = v.x * sc.x + sh.x;
    v.y = v.y * sc.y + sh.y;
    v.z = v.z * sc.z + sh.z;
    v.w = v.w * sc.w + sh.w;
    ((float4*)out)[i] = v;
}

// ---------------- launch ----------------
extern "C" void kernel_launch(void* const* d_in, const int* in_sizes, int n_in,
                              void* d_out, int out_size) {
    const float* x     = (const float*)d_in[0];
    const int*   ei    = (const int*)d_in[1];     // int32! (JAX x64 disabled)
    const float* ew    = (const float*)d_in[2];
    const float* W     = (const float*)d_in[3];
    const float* gamma = (const float*)d_in[4];
    const float* beta  = (const float*)d_in[5];
    float*       out   = (float*)d_out;

    const int SCAN_BLOCKS = (N_NODES + 1023) / 1024;   // 98

    k_init<<<(N_NODES + 255) / 256, 256>>>();
    k_gemm<<<N_NODES / 16, 128>>>(x, W);
    k_degcnt<<<(N_EDGES + 255) / 256, 256>>>(ei);
    k_dinv<<<(N_NODES + 255) / 256, 256>>>();
    k_scan1<<<SCAN_BLOCKS, 1024>>>();
    k_scan2<<<1, 32>>>(SCAN_BLOCKS);
    k_scan3<<<SCAN_BLOCKS, 1024>>>();
    k_scatter<<<(N_EDGES + 255) / 256, 256>>>(ei, ew);
    k_agg<<<N_NODES / 8, 256>>>(out);
    k_bnparam<<<1, 64>>>(gamma, beta);
    k_bnapply<<<(N_NODES * F_OUT / 4 + 255) / 256, 256>>>(out);
}

// round 4
// speedup vs baseline: 1.9688x; 1.9688x over previous
#include <cuda_runtime.h>
#include <cuda_bf16.h>

#define N_NODES 100000
#define N_EDGES 1600000
#define F_IN 128
#define F_OUT 64
#define BN_EPS 1e-5f

// ---------------- scratch ----------------
__device__ __align__(16) float g_h[N_NODES * F_OUT];     // 25.6 MB
__device__ __align__(16) float g_dinv[N_NODES];
__device__ __align__(16) int   g_deg[N_NODES];
__device__ __align__(16) int   g_cnt[N_NODES];
__device__ __align__(16) int   g_rowptr[N_NODES + 1];
__device__ __align__(16) int   g_cursor[N_NODES];
__device__ __align__(16) unsigned long long g_edge[N_EDGES];  // packed (coef<<32)|src
__device__ __align__(16) int   g_bsum[128];
__device__ __align__(16) float g_sum[F_OUT];
__device__ __align__(16) float g_sumsq[F_OUT];

// ---------------- init ----------------
__global__ void k_init() {
    int i = blockIdx.x * blockDim.x + threadIdx.x;
    if (i < N_NODES) {
        g_deg[i] = 1;
        g_cnt[i] = 0;
    }
    if (i < F_OUT) {
        g_sum[i] = 0.f;
        g_sumsq[i] = 0.f;
    }
}

// ---------------- degree + dst histogram (edge_index is int32) ----------------
__global__ void k_degcnt(const int* __restrict__ ei) {
    int e = blockIdx.x * blockDim.x + threadIdx.x;
    if (e >= N_EDGES) return;
    int s = ei[e];
    int d = ei[N_EDGES + e];
    atomicAdd(&g_deg[s], 1);
    atomicAdd(&g_cnt[d], 1);
}

// ---------------- scan level 1 (+ fused dinv) ----------------
__global__ void k_scan1() {
    __shared__ int s[1024];
    int i = blockIdx.x * 1024 + threadIdx.x;
    if (i < N_NODES) g_dinv[i] = rsqrtf((float)g_deg[i]);   // fused
    int v = (i < N_NODES) ? g_cnt[i] : 0;
    s[threadIdx.x] = v;
    __syncthreads();
    for (int off = 512; off > 0; off >>= 1) {
        if (threadIdx.x < off) s[threadIdx.x] += s[threadIdx.x + off];
        __syncthreads();
    }
    if (threadIdx.x == 0) g_bsum[blockIdx.x] = s[0];
}

__global__ void k_scan2(int nblocks) {
    if (threadIdx.x == 0) {
        int acc = 0;
        for (int b = 0; b < nblocks; b++) {
            int v = g_bsum[b];
            g_bsum[b] = acc;
            acc += v;
        }
        g_rowptr[N_NODES] = acc;
    }
}

__global__ void k_scan3() {
    __shared__ int s[1024];
    int i = blockIdx.x * 1024 + threadIdx.x;
    int v = (i < N_NODES) ? g_cnt[i] : 0;
    s[threadIdx.x] = v;
    __syncthreads();
    for (int off = 1; off < 1024; off <<= 1) {
        int t = (threadIdx.x >= off) ? s[threadIdx.x - off] : 0;
        __syncthreads();
        s[threadIdx.x] += t;
        __syncthreads();
    }
    if (i < N_NODES) {
        int out = g_bsum[blockIdx.x] + s[threadIdx.x] - v;
        g_rowptr[i] = out;
        g_cursor[i] = out;
    }
}

// ---------------- scatter edges (packed 8B per edge) ----------------
__global__ void k_scatter(const int* __restrict__ ei,
                          const float* __restrict__ ew) {
    int e = blockIdx.x * blockDim.x + threadIdx.x;
    if (e >= N_EDGES) return;
    int s = ei[e];
    int d = ei[N_EDGES + e];
    float c = g_dinv[s] * ew[e] * g_dinv[d];
    int p = atomicAdd(&g_cursor[d], 1);
    g_edge[p] = ((unsigned long long)__float_as_uint(c) << 32) | (unsigned)s;
}

// ---------------- GEMM: h = x @ W^T  (32 nodes/block, 4x4 per thread) ----------------
__global__ __launch_bounds__(128) void k_gemm(const float* __restrict__ x,
                                              const float* __restrict__ W) {
    __shared__ float sW[F_IN * F_OUT];   // sW[k*64+o], 32 KB
    __shared__ float sX[32 * F_IN];      // 16 KB   (total 48 KB)
    int tid = threadIdx.x;
    int lane = tid & 31;
    int w = tid >> 5;

    // lane-major transpose fill: conflict-free STS (bank = o%32, distinct per lane)
    for (int kc = w; kc < 32; kc += 4) {
        #pragma unroll
        for (int oh = 0; oh < 2; oh++) {
            int o = lane + oh * 32;
            float4 wv = *(const float4*)&W[o * F_IN + kc * 4];
            sW[(kc * 4 + 0) * F_OUT + o] = wv.x;
            sW[(kc * 4 + 1) * F_OUT + o] = wv.y;
            sW[(kc * 4 + 2) * F_OUT + o] = wv.z;
            sW[(kc * 4 + 3) * F_OUT + o] = wv.w;
        }
    }
    int nodeBase = blockIdx.x * 32;
    const float4* x4 = (const float4*)(x + (size_t)nodeBase * F_IN);
    float4* sX4 = (float4*)sX;
    #pragma unroll
    for (int i = tid; i < 32 * F_IN / 4; i += 128) sX4[i] = x4[i];
    __syncthreads();

    int og = tid & 15;        // outs og*4..og*4+3
    int ng = tid >> 4;        // nodes ng*4..ng*4+3
    float acc[4][4];
    #pragma unroll
    for (int a = 0; a < 4; a++)
        #pragma unroll
        for (int b = 0; b < 4; b++) acc[a][b] = 0.f;

    #pragma unroll 4
    for (int k = 0; k < F_IN; k++) {
        float4 w4 = *(const float4*)&sW[k * F_OUT + og * 4];
        #pragma unroll
        for (int ni = 0; ni < 4; ni++) {
            float xv = sX[(ng * 4 + ni) * F_IN + k];
            acc[ni][0] += xv * w4.x;
            acc[ni][1] += xv * w4.y;
            acc[ni][2] += xv * w4.z;
            acc[ni][3] += xv * w4.w;
        }
    }
    #pragma unroll
    for (int ni = 0; ni < 4; ni++) {
        int node = nodeBase + ng * 4 + ni;
        *(float4*)&g_h[(size_t)node * F_OUT + og * 4] =
            make_float4(acc[ni][0], acc[ni][1], acc[ni][2], acc[ni][3]);
    }
}

// ---------------- aggregation: warp/node, unroll-4 gathers (MLP 4) ----------------
__global__ __launch_bounds__(256) void k_agg(float* __restrict__ out) {
    __shared__ float s_psum[8][F_OUT];
    __shared__ float s_psq[8][F_OUT];
    int tid = threadIdx.x;
    int warp = tid >> 5;
    int lane = tid & 31;
    int node = blockIdx.x * 8 + warp;   // 12500 * 8 = 100000

    const float2* h2 = (const float2*)g_h;
    float ax, ay;
    {
        float di = g_dinv[node];
        float c = di * di;
        float2 hv = h2[(size_t)node * 32 + lane];
        ax = hv.x * c;
        ay = hv.y * c;
    }
    int e = g_rowptr[node];
    int end = g_rowptr[node + 1];

    for (; e + 4 <= end; e += 4) {
        unsigned long long p0 = g_edge[e];
        unsigned long long p1 = g_edge[e + 1];
        unsigned long long p2 = g_edge[e + 2];
        unsigned long long p3 = g_edge[e + 3];
        int s0 = (int)(unsigned)p0; float c0 = __uint_as_float((unsigned)(p0 >> 32));
        int s1 = (int)(unsigned)p1; float c1 = __uint_as_float((unsigned)(p1 >> 32));
        int s2 = (int)(unsigned)p2; float c2 = __uint_as_float((unsigned)(p2 >> 32));
        int s3 = (int)(unsigned)p3; float c3 = __uint_as_float((unsigned)(p3 >> 32));
        float2 v0 = h2[(size_t)s0 * 32 + lane];
        float2 v1 = h2[(size_t)s1 * 32 + lane];
        float2 v2 = h2[(size_t)s2 * 32 + lane];
        float2 v3 = h2[(size_t)s3 * 32 + lane];
        ax += v0.x * c0; ay += v0.y * c0;
        ax += v1.x * c1; ay += v1.y * c1;
        ax += v2.x * c2; ay += v2.y * c2;
        ax += v3.x * c3; ay += v3.y * c3;
    }
    for (; e < end; e++) {
        unsigned long long p = g_edge[e];
        int s = (int)(unsigned)p;
        float c = __uint_as_float((unsigned)(p >> 32));
        float2 hv = h2[(size_t)s * 32 + lane];
        ax += hv.x * c;
        ay += hv.y * c;
    }
    ax = fmaxf(ax, 0.f);
    ay = fmaxf(ay, 0.f);

    ((float2*)out)[(size_t)node * 32 + lane] = make_float2(ax, ay);

    s_psum[warp][2 * lane]     = ax;
    s_psum[warp][2 * lane + 1] = ay;
    s_psq[warp][2 * lane]      = ax * ax;
    s_psq[warp][2 * lane + 1]  = ay * ay;
    __syncthreads();
    if (tid < F_OUT) {
        float a = 0.f, b = 0.f;
        #pragma unroll
        for (int w = 0; w < 8; w++) {
            a += s_psum[w][tid];
            b += s_psq[w][tid];
        }
        atomicAdd(&g_sum[tid], a);
        atomicAdd(&g_sumsq[tid], b);
    }
}

// ---------------- BN: params computed per-block + apply (fused) ----------------
__global__ __launch_bounds__(256) void k_bnapply(float* __restrict__ out,
                                                 const float* __restrict__ gamma,
                                                 const float* __restrict__ beta) {
    __shared__ float s_scale[F_OUT];
    __shared__ float s_shift[F_OUT];
    int tid = threadIdx.x;
    if (tid < F_OUT) {
        float invN = 1.0f / (float)N_NODES;
        float mean = g_sum[tid] * invN;
        float var = g_sumsq[tid] * invN - mean * mean;
        float sc = gamma[tid] * rsqrtf(var + BN_EPS);
        s_scale[tid] = sc;
        s_shift[tid] = beta[tid] - mean * sc;
    }
    __syncthreads();
    int i = blockIdx.x * blockDim.x + tid;   // float4 index
    if (i >= N_NODES * F_OUT / 4) return;
    int f4 = (i & 15) * 4;
    float4 v = ((float4*)out)[i];
    v.x = v.x * s_scale[f4 + 0] + s_shift[f4 + 0];
    v.y = v.y * s_scale[f4 + 1] + s_shift[f4 + 1];
    v.z = v.z * s_scale[f4 + 2] + s_shift[f4 + 2];
    v.w = v.w * s_scale[f4 + 3] + s_shift[f4 + 3];
    ((float4*)out)[i] = v;
}

// ---------------- launch ----------------
extern "C" void kernel_launch(void* const* d_in, const int* in_sizes, int n_in,
                              void* d_out, int out_size) {
    const float* x     = (const float*)d_in[0];
    const int*   ei    = (const int*)d_in[1];     // int32 (JAX x64 disabled)
    const float* ew    = (const float*)d_in[2];
    const float* W     = (const float*)d_in[3];
    const float* gamma = (const float*)d_in[4];
    const float* beta  = (const float*)d_in[5];
    float*       out   = (float*)d_out;

    const int SCAN_BLOCKS = (N_NODES + 1023) / 1024;   // 98

    k_init<<<(N_NODES + 255) / 256, 256>>>();
    k_degcnt<<<(N_EDGES + 255) / 256, 256>>>(ei);
    k_gemm<<<N_NODES / 32, 128>>>(x, W);
    k_scan1<<<SCAN_BLOCKS, 1024>>>();
    k_scan2<<<1, 32>>>(SCAN_BLOCKS);
    k_scan3<<<SCAN_BLOCKS, 1024>>>();
    k_scatter<<<(N_EDGES + 255) / 256, 256>>>(ei, ew);
    k_agg<<<N_NODES / 8, 256>>>(out);
    k_bnapply<<<(N_NODES * F_OUT / 4 + 255) / 256, 256>>>(out, gamma, beta);
}

// round 5
// speedup vs baseline: 2.1948x; 1.1148x over previous
#include <cuda_runtime.h>
#include <cuda_bf16.h>

#define N_NODES 100000
#define N_EDGES 1600000
#define F_IN 128
#define F_OUT 64
#define BN_EPS 1e-5f

#define GEMM_BLOCKS 3125          // 32 nodes each
#define EDGE_BLOCKS 3125          // 512 edges each

// ---------------- scratch ----------------
__device__ __align__(16) float g_h[N_NODES * F_OUT];     // 25.6 MB
__device__ __align__(16) float g_dinv[N_NODES];
__device__ __align__(16) int   g_deg[N_NODES];
__device__ __align__(16) int   g_cnt[N_NODES];
__device__ __align__(16) int   g_rowptr[N_NODES + 1];
__device__ __align__(16) int   g_cursor[N_NODES];
__device__ __align__(16) unsigned long long g_edge[N_EDGES];  // packed (coef<<32)|src
__device__ __align__(16) int   g_bsum[128];
__device__ __align__(16) float g_sum[F_OUT];
__device__ __align__(16) float g_sumsq[F_OUT];

// ---------------- init ----------------
__global__ void k_init() {
    int i = blockIdx.x * blockDim.x + threadIdx.x;
    if (i < N_NODES) {
        g_deg[i] = 1;
        g_cnt[i] = 0;
    }
    if (i < F_OUT) {
        g_sum[i] = 0.f;
        g_sumsq[i] = 0.f;
    }
    if (i == 0) g_rowptr[N_NODES] = N_EDGES;
}

// ---------------- fused GEMM + degree/histogram ----------------
// blocks [0, GEMM_BLOCKS): h = x @ W^T, 32 nodes/block, f32x2 packed FMA
// blocks [GEMM_BLOCKS, GEMM_BLOCKS+EDGE_BLOCKS): degree + dst histogram
__global__ __launch_bounds__(128) void k_gemm_deg(const float* __restrict__ x,
                                                  const float* __restrict__ W,
                                                  const int* __restrict__ ei) {
    __shared__ float sW[F_IN * F_OUT];   // [k][o], 32 KB
    __shared__ float sX[32 * F_IN];      // [node][k], 16 KB
    int tid = threadIdx.x;

    if (blockIdx.x >= GEMM_BLOCKS) {
        // ---- degcnt role ----
        int base = (blockIdx.x - GEMM_BLOCKS) * 512;
        #pragma unroll
        for (int r = 0; r < 4; r++) {
            int e = base + r * 128 + tid;
            int s = ei[e];
            int d = ei[N_EDGES + e];
            atomicAdd(&g_deg[s], 1);
            atomicAdd(&g_cnt[d], 1);
        }
        return;
    }

    // ---- GEMM role ----
    int lane = tid & 31;
    int w = tid >> 5;
    // transpose fill of sW: lane-major => conflict-free STS
    for (int kc = w; kc < 32; kc += 4) {
        #pragma unroll
        for (int oh = 0; oh < 2; oh++) {
            int o = lane + oh * 32;
            float4 wv = *(const float4*)&W[o * F_IN + kc * 4];
            sW[(kc * 4 + 0) * F_OUT + o] = wv.x;
            sW[(kc * 4 + 1) * F_OUT + o] = wv.y;
            sW[(kc * 4 + 2) * F_OUT + o] = wv.z;
            sW[(kc * 4 + 3) * F_OUT + o] = wv.w;
        }
    }
    int nodeBase = blockIdx.x * 32;
    const float4* x4 = (const float4*)(x + (size_t)nodeBase * F_IN);
    float4* sX4 = (float4*)sX;
    #pragma unroll
    for (int i = tid; i < 32 * F_IN / 4; i += 128) sX4[i] = x4[i];
    __syncthreads();

    int og = tid & 15;        // outs og*4..og*4+3  (2 packed pairs)
    int ng = tid >> 4;        // nodes ng*4..ng*4+3

    // acc[node][outpair] as packed f32x2 (zero bits == (0.f,0.f))
    unsigned long long acc[4][2];
    #pragma unroll
    for (int a = 0; a < 4; a++) { acc[a][0] = 0ull; acc[a][1] = 0ull; }

    #pragma unroll 4
    for (int k = 0; k < F_IN; k += 2) {
        ulonglong2 wA = *(const ulonglong2*)&sW[k * F_OUT + og * 4];        // k:   outs og*4..+3
        ulonglong2 wB = *(const ulonglong2*)&sW[(k + 1) * F_OUT + og * 4];  // k+1
        #pragma unroll
        for (int ni = 0; ni < 4; ni++) {
            float2 xv = *(const float2*)&sX[(ng * 4 + ni) * F_IN + k];
            unsigned long long x0d, x1d;
            unsigned x0 = __float_as_uint(xv.x);
            unsigned x1 = __float_as_uint(xv.y);
            asm("mov.b64 %0, {%1, %1};" : "=l"(x0d) : "r"(x0));
            asm("mov.b64 %0, {%1, %1};" : "=l"(x1d) : "r"(x1));
            asm("fma.rn.f32x2 %0, %1, %2, %0;" : "+l"(acc[ni][0]) : "l"(wA.x), "l"(x0d));
            asm("fma.rn.f32x2 %0, %1, %2, %0;" : "+l"(acc[ni][1]) : "l"(wA.y), "l"(x0d));
            asm("fma.rn.f32x2 %0, %1, %2, %0;" : "+l"(acc[ni][0]) : "l"(wB.x), "l"(x1d));
            asm("fma.rn.f32x2 %0, %1, %2, %0;" : "+l"(acc[ni][1]) : "l"(wB.y), "l"(x1d));
        }
    }
    #pragma unroll
    for (int ni = 0; ni < 4; ni++) {
        int node = nodeBase + ng * 4 + ni;
        unsigned a0, a1, a2, a3;
        asm("mov.b64 {%0, %1}, %2;" : "=r"(a0), "=r"(a1) : "l"(acc[ni][0]));
        asm("mov.b64 {%0, %1}, %2;" : "=r"(a2), "=r"(a3) : "l"(acc[ni][1]));
        *(float4*)&g_h[(size_t)node * F_OUT + og * 4] =
            make_float4(__uint_as_float(a0), __uint_as_float(a1),
                        __uint_as_float(a2), __uint_as_float(a3));
    }
}

// ---------------- scan level 1 (+ fused dinv) ----------------
__global__ void k_scan1() {
    __shared__ int s[1024];
    int i = blockIdx.x * 1024 + threadIdx.x;
    if (i < N_NODES) g_dinv[i] = rsqrtf((float)g_deg[i]);
    int v = (i < N_NODES) ? g_cnt[i] : 0;
    s[threadIdx.x] = v;
    __syncthreads();
    for (int off = 512; off > 0; off >>= 1) {
        if (threadIdx.x < off) s[threadIdx.x] += s[threadIdx.x + off];
        __syncthreads();
    }
    if (threadIdx.x == 0) g_bsum[blockIdx.x] = s[0];
}

// ---------------- scan level 2 fused into level 3 ----------------
__global__ void k_scan3() {
    __shared__ int s[1024];
    __shared__ int sbase;
    int b = blockIdx.x;
    if (threadIdx.x < 32) {
        int acc = 0;
        for (int j = threadIdx.x; j < b; j += 32) acc += g_bsum[j];
        #pragma unroll
        for (int off = 16; off > 0; off >>= 1)
            acc += __shfl_xor_sync(0xffffffffu, acc, off);
        if (threadIdx.x == 0) sbase = acc;
    }
    int i = b * 1024 + threadIdx.x;
    int v = (i < N_NODES) ? g_cnt[i] : 0;
    s[threadIdx.x] = v;
    __syncthreads();
    for (int off = 1; off < 1024; off <<= 1) {
        int t = (threadIdx.x >= off) ? s[threadIdx.x - off] : 0;
        __syncthreads();
        s[threadIdx.x] += t;
        __syncthreads();
    }
    if (i < N_NODES) {
        int out = sbase + s[threadIdx.x] - v;   // exclusive
        g_rowptr[i] = out;
        g_cursor[i] = out;
    }
}

// ---------------- scatter edges (packed 8B per edge) ----------------
__global__ void k_scatter(const int* __restrict__ ei,
                          const float* __restrict__ ew) {
    int e = blockIdx.x * blockDim.x + threadIdx.x;
    if (e >= N_EDGES) return;
    int s = ei[e];
    int d = ei[N_EDGES + e];
    float c = g_dinv[s] * ew[e] * g_dinv[d];
    int p = atomicAdd(&g_cursor[d], 1);
    g_edge[p] = ((unsigned long long)__float_as_uint(c) << 32) | (unsigned)s;
}

// ---------------- aggregation: warp/node, unroll-4 gathers ----------------
__global__ __launch_bounds__(256) void k_agg(float* __restrict__ out) {
    __shared__ float s_psum[8][F_OUT];
    __shared__ float s_psq[8][F_OUT];
    int tid = threadIdx.x;
    int warp = tid >> 5;
    int lane = tid & 31;
    int node = blockIdx.x * 8 + warp;   // 12500 * 8 = 100000

    const float2* h2 = (const float2*)g_h;
    float ax, ay;
    {
        float di = g_dinv[node];
        float c = di * di;
        float2 hv = h2[(size_t)node * 32 + lane];
        ax = hv.x * c;
        ay = hv.y * c;
    }
    int e = g_rowptr[node];
    int end = g_rowptr[node + 1];

    for (; e + 4 <= end; e += 4) {
        unsigned long long p0 = g_edge[e];
        unsigned long long p1 = g_edge[e + 1];
        unsigned long long p2 = g_edge[e + 2];
        unsigned long long p3 = g_edge[e + 3];
        int s0 = (int)(unsigned)p0; float c0 = __uint_as_float((unsigned)(p0 >> 32));
        int s1 = (int)(unsigned)p1; float c1 = __uint_as_float((unsigned)(p1 >> 32));
        int s2 = (int)(unsigned)p2; float c2 = __uint_as_float((unsigned)(p2 >> 32));
        int s3 = (int)(unsigned)p3; float c3 = __uint_as_float((unsigned)(p3 >> 32));
        float2 v0 = h2[(size_t)s0 * 32 + lane];
        float2 v1 = h2[(size_t)s1 * 32 + lane];
        float2 v2 = h2[(size_t)s2 * 32 + lane];
        float2 v3 = h2[(size_t)s3 * 32 + lane];
        ax += v0.x * c0; ay += v0.y * c0;
        ax += v1.x * c1; ay += v1.y * c1;
        ax += v2.x * c2; ay += v2.y * c2;
        ax += v3.x * c3; ay += v3.y * c3;
    }
    for (; e < end; e++) {
        unsigned long long p = g_edge[e];
        int s = (int)(unsigned)p;
        float c = __uint_as_float((unsigned)(p >> 32));
        float2 hv = h2[(size_t)s * 32 + lane];
        ax += hv.x * c;
        ay += hv.y * c;
    }
    ax = fmaxf(ax, 0.f);
    ay = fmaxf(ay, 0.f);

    ((float2*)out)[(size_t)node * 32 + lane] = make_float2(ax, ay);

    s_psum[warp][2 * lane]     = ax;
    s_psum[warp][2 * lane + 1] = ay;
    s_psq[warp][2 * lane]      = ax * ax;
    s_psq[warp][2 * lane + 1]  = ay * ay;
    __syncthreads();
    if (tid < F_OUT) {
        float a = 0.f, b = 0.f;
        #pragma unroll
        for (int w = 0; w < 8; w++) {
            a += s_psum[w][tid];
            b += s_psq[w][tid];
        }
        atomicAdd(&g_sum[tid], a);
        atomicAdd(&g_sumsq[tid], b);
    }
}

// ---------------- BN: params per-block + apply ----------------
__global__ __launch_bounds__(256) void k_bnapply(float* __restrict__ out,
                                                 const float* __restrict__ gamma,
                                                 const float* __restrict__ beta) {
    __shared__ float s_scale[F_OUT];
    __shared__ float s_shift[F_OUT];
    int tid = threadIdx.x;
    if (tid < F_OUT) {
        float invN = 1.0f / (float)N_NODES;
        float mean = g_sum[tid] * invN;
        float var = g_sumsq[tid] * invN - mean * mean;
        float sc = gamma[tid] * rsqrtf(var + BN_EPS);
        s_scale[tid] = sc;
        s_shift[tid] = beta[tid] - mean * sc;
    }
    __syncthreads();
    int i = blockIdx.x * blockDim.x + tid;   // float4 index
    if (i >= N_NODES * F_OUT / 4) return;
    int f4 = (i & 15) * 4;
    float4 v = ((float4*)out)[i];
    v.x = v.x * s_scale[f4 + 0] + s_shift[f4 + 0];
    v.y = v.y * s_scale[f4 + 1] + s_shift[f4 + 1];
    v.z = v.z * s_scale[f4 + 2] + s_shift[f4 + 2];
    v.w = v.w * s_scale[f4 + 3] + s_shift[f4 + 3];
    ((float4*)out)[i] = v;
}

// ---------------- launch ----------------
extern "C" void kernel_launch(void* const* d_in, const int* in_sizes, int n_in,
                              void* d_out, int out_size) {
    const float* x     = (const float*)d_in[0];
    const int*   ei    = (const int*)d_in[1];     // int32 (JAX x64 disabled)
    const float* ew    = (const float*)d_in[2];
    const float* W     = (const float*)d_in[3];
    const float* gamma = (const float*)d_in[4];
    const float* beta  = (const float*)d_in[5];
    float*       out   = (float*)d_out;

    const int SCAN_BLOCKS = (N_NODES + 1023) / 1024;   // 98

    k_init<<<(N_NODES + 255) / 256, 256>>>();
    k_gemm_deg<<<GEMM_BLOCKS + EDGE_BLOCKS, 128>>>(x, W, ei);
    k_scan1<<<SCAN_BLOCKS, 1024>>>();
    k_scan3<<<SCAN_BLOCKS, 1024>>>();
    k_scatter<<<(N_EDGES + 255) / 256, 256>>>(ei, ew);
    k_agg<<<N_NODES / 8, 256>>>(out);
    k_bnapply<<<(N_NODES * F_OUT / 4 + 255) / 256, 256>>>(out, gamma, beta);
}